// round 15
// baseline (speedup 1.0000x reference)
#include <cuda_runtime.h>

#define W_ 256
#define H_ 256
#define HW_ 65536
#define B_ 4
#define C_ 256
#define R_ 32
#define K_ 6

// 64 MB zipped scratch: {stardist, conf0} per (b,r,pixel).
__device__ float2 g_zip[B_ * R_ * HW_];
__device__ float g_sin[R_];
__device__ float g_cos[R_];

__constant__ float c_ef[5] = {0.2f, 0.4f, 0.6f, 0.8f, 1.0f};

__device__ __forceinline__ float tf32r(float x)
{
    unsigned u;
    asm("cvt.rna.tf32.f32 %0, %1;" : "=r"(u) : "f"(x));
    return __uint_as_float(u);
}

// ---- packed f32x2 helpers ----
__device__ __forceinline__ unsigned long long pack2(float lo, float hi)
{
    unsigned long long r;
    asm("mov.b64 %0, {%1, %2};" : "=l"(r) : "f"(lo), "f"(hi));
    return r;
}
__device__ __forceinline__ void unpack2(unsigned long long v, float& lo, float& hi)
{
    asm("mov.b64 {%0, %1}, %2;" : "=f"(lo), "=f"(hi) : "l"(v));
}
__device__ __forceinline__ unsigned long long mul2(unsigned long long a, unsigned long long b)
{
    unsigned long long d;
    asm("mul.rn.f32x2 %0, %1, %2;" : "=l"(d) : "l"(a), "l"(b));
    return d;
}
__device__ __forceinline__ unsigned long long add2(unsigned long long a, unsigned long long b)
{
    unsigned long long d;
    asm("add.rn.f32x2 %0, %1, %2;" : "=l"(d) : "l"(a), "l"(b));
    return d;
}
__device__ __forceinline__ void fma2(unsigned long long& d,
                                     unsigned long long a,
                                     unsigned long long b)
{
    asm("fma.rn.f32x2 %0, %1, %2, %0;" : "+l"(d) : "l"(a), "l"(b));
}

// ---- conf0 (per batch): TF32 MMA, warp-private 3-stage cp.async pipeline,
// SMEM-staged coalesced zip epilogue. Identical arithmetic to round 14.
#define W0S_FLOATS (R_ * 257)
#define FS_ROW      72
#define FS_STAGE_W  (8 * FS_ROW)
#define FS_WSLICE   (3 * FS_STAGE_W)
#define FS_FLOATS   (8 * FS_WSLICE)
#define SMEM_FLOATS (W0S_FLOATS + FS_FLOATS)
#define ES_ROW      66

__global__ __launch_bounds__(256) void conf0_mma_kernel(
    const float* __restrict__ features,
    const float* __restrict__ w0,
    const float* __restrict__ sd,
    int batch)
{
    extern __shared__ float smem[];
    float* w0s = smem;
    float* fs  = smem + W0S_FLOATS;

    if (blockIdx.x == 0 && threadIdx.x < R_) {
        int r = threadIdx.x;
        float ang = __fmul_rn(__fdiv_rn((float)r, 32.0f), 6.28318530717958647692f);
        g_sin[r] = sinf(ang);
        g_cos[r] = cosf(ang);
    }

    int tid  = threadIdx.x;
    int wi   = tid >> 5;
    int lane = tid & 31;
    int grp  = lane >> 2;
    int tg   = lane & 3;

    for (int i = tid; i < R_ * C_; i += 256)
        w0s[(i >> 8) * 257 + (i & 255)] = tf32r(w0[i]);
    __syncthreads();

    int b    = batch;
    int pix0 = blockIdx.x * 512 + wi * 64;

    const float* fb = features + (size_t)b * C_ * HW_ + pix0;
    float* fwarp = fs + wi * FS_WSLICE;
    unsigned fsw = (unsigned)__cvta_generic_to_shared(fwarp);

    float c[2][8][4];
#pragma unroll
    for (int mt = 0; mt < 2; mt++)
#pragma unroll
        for (int nt = 0; nt < 8; nt++)
#pragma unroll
            for (int i = 0; i < 4; i++) c[mt][nt][i] = 0.0f;

#define LOAD_STAGE(st, ch0)                                                      \
    {                                                                            \
        _Pragma("unroll")                                                        \
        for (int i = 0; i < 4; i++) {                                            \
            int e   = lane + 32 * i;                                             \
            int row = e >> 4;                                                    \
            int f4  = e & 15;                                                    \
            const float* g = fb + (size_t)((ch0) + row) * HW_ + f4 * 4;          \
            unsigned s = fsw + (unsigned)(((st) * FS_STAGE_W + row * FS_ROW) * 4 + f4 * 16); \
            asm volatile("cp.async.cg.shared.global [%0], [%1], 16;"             \
                         :: "r"(s), "l"(g));                                     \
        }                                                                        \
    }

#pragma unroll
    for (int st = 0; st < 2; st++) {
        LOAD_STAGE(st, st * 8);
        asm volatile("cp.async.commit_group;");
    }

    int cur = 0;
#pragma unroll 4
    for (int k8 = 0; k8 < 32; k8++) {
        if (k8 + 2 < 32) {
            int stn = (k8 + 2) % 3;
            LOAD_STAGE(stn, (k8 + 2) * 8);
        }
        asm volatile("cp.async.commit_group;");
        asm volatile("cp.async.wait_group 2;");
        __syncwarp();

        const float* fcur = fwarp + cur * FS_STAGE_W;
        cur = (cur == 2) ? 0 : cur + 1;

        int ch = k8 * 8 + tg;
        unsigned a[2][4];
#pragma unroll
        for (int mt = 0; mt < 2; mt++) {
            int ray0 = mt * 16 + grp;
            a[mt][0] = __float_as_uint(w0s[ray0 * 257 + ch]);
            a[mt][1] = __float_as_uint(w0s[(ray0 + 8) * 257 + ch]);
            a[mt][2] = __float_as_uint(w0s[ray0 * 257 + ch + 4]);
            a[mt][3] = __float_as_uint(w0s[(ray0 + 8) * 257 + ch + 4]);
        }

#pragma unroll
        for (int nt = 0; nt < 8; nt++) {
            int col = nt * 8 + grp;
            unsigned b0 = __float_as_uint(tf32r(fcur[tg * FS_ROW + col]));
            unsigned b1 = __float_as_uint(tf32r(fcur[(tg + 4) * FS_ROW + col]));
#pragma unroll
            for (int mt = 0; mt < 2; mt++) {
                asm volatile(
                    "mma.sync.aligned.m16n8k8.row.col.f32.tf32.tf32.f32 "
                    "{%0,%1,%2,%3}, {%4,%5,%6,%7}, {%8,%9}, {%0,%1,%2,%3};"
                    : "+f"(c[mt][nt][0]), "+f"(c[mt][nt][1]),
                      "+f"(c[mt][nt][2]), "+f"(c[mt][nt][3])
                    : "r"(a[mt][0]), "r"(a[mt][1]), "r"(a[mt][2]), "r"(a[mt][3]),
                      "r"(b0), "r"(b1));
            }
        }
    }

    const float* sdb = sd + (size_t)b * R_ * HW_ + pix0;
    float2* zb = g_zip + (size_t)b * R_ * HW_ + pix0;
    float* es = fwarp;

#pragma unroll
    for (int mt = 0; mt < 2; mt++) {
        __syncwarp();
#pragma unroll
        for (int nt = 0; nt < 8; nt++) {
            int col = nt * 8 + tg * 2;
            *(float2*)&es[grp * ES_ROW + col]       = make_float2(c[mt][nt][0], c[mt][nt][1]);
            *(float2*)&es[(grp + 8) * ES_ROW + col] = make_float2(c[mt][nt][2], c[mt][nt][3]);
        }
        __syncwarp();
#pragma unroll
        for (int rr = 0; rr < 16; rr++) {
            int ray = mt * 16 + rr;
            int px  = lane * 2;
            float2 cv = *(float2*)&es[rr * ES_ROW + px];
            float2 sv = *(const float2*)(sdb + (size_t)ray * HW_ + px);
            float4 o  = make_float4(sv.x, cv.x, sv.y, cv.y);
            *(float4*)(zb + (size_t)ray * HW_ + px) = o;
        }
    }
}

// Kernel 2 (per batch): fused refine — arithmetic identical to round 13/14.
__global__ __launch_bounds__(256) void refine_kernel(
    const float* __restrict__ w1,
    const float* __restrict__ b1,
    float* __restrict__ ray_out,
    float* __restrict__ conf_out,
    int batch)
{
    __shared__ float2 w1p[K_ * 3];
    __shared__ float b1s[K_];
    if (threadIdx.x < K_ * 3) {
        int k = threadIdx.x / 3, p = threadIdx.x % 3;
        w1p[k * 3 + p] = make_float2(w1[(2 * p) * K_ + k], w1[(2 * p + 1) * K_ + k]);
    }
    if (threadIdx.x < K_) b1s[threadIdx.x] = b1[threadIdx.x];
    __syncthreads();

    int t = batch * (R_ * HW_) + blockIdx.x * blockDim.x + threadIdx.x;
    int w = t & (W_ - 1);
    int h = (t >> 8) & (H_ - 1);
    int r = (t >> 16) & (R_ - 1);

    float2 sc = g_zip[t];
    float s  = sc.x;
    float c0 = sc.y;

    unsigned long long cssn = pack2(g_cos[r], g_sin[r]);
    unsigned long long wh   = pack2((float)w, (float)h);

    const float2* plane_z = g_zip + (t & ~(HW_ - 1));

    float rays[K_], confs[K_];
    rays[0]  = s;
    confs[0] = c0;

    const float INV255 = 1.0f / 255.0f;
    const unsigned long long inv255_2 = pack2(INV255, INV255);
    const unsigned long long two2  = pack2(2.0f, 2.0f);
    const unsigned long long neg12 = pack2(-1.0f, -1.0f);
    const unsigned long long one2  = pack2(1.0f, 1.0f);
    const unsigned long long c2562 = pack2(256.0f, 256.0f);
    const unsigned long long half2 = pack2(0.5f, 0.5f);

#pragma unroll
    for (int e = 0; e < 5; e++) {
        float ef   = c_ef[e];
        float base = __fmul_rn(__fadd_rn(s, -1.0f), ef);
        unsigned long long base2 = pack2(base, base);
        unsigned long long g2 = add2(wh, mul2(cssn, base2));
        unsigned long long n2 = add2(mul2(mul2(g2, inv255_2), two2), neg12);
        unsigned long long i2 = mul2(add2(mul2(add2(n2, one2), c2562), neg12), half2);
        float ixf, iyf;
        unpack2(i2, ixf, iyf);
        int ix0 = __float2int_rn(ixf);
        int iy0 = __float2int_rn(iyf);
        bool valid = ((unsigned)ix0 < 256u) && ((unsigned)iy0 < 256u);
        int gi = valid ? (iy0 * W_ + ix0) : 0;
        float2 g = __ldg(&plane_z[gi]);
        float ss = valid ? g.x : 0.0f;
        float cc = valid ? g.y : 0.0f;
        rays[e + 1]  = __fadd_rn(ss, base);
        confs[e + 1] = cc;
    }

    unsigned long long zp[3];
    zp[0] = zp[1] = zp[2] = pack2(0.0f, 0.0f);
#pragma unroll
    for (int k = 0; k < K_; k++) {
        unsigned long long ck = pack2(confs[k], confs[k]);
#pragma unroll
        for (int p = 0; p < 3; p++) {
            float2 wv = w1p[k * 3 + p];
            fma2(zp[p], ck, pack2(wv.x, wv.y));
        }
    }
    float z[K_];
#pragma unroll
    for (int p = 0; p < 3; p++) {
        float lo, hi;
        unpack2(zp[p], lo, hi);
        z[2 * p]     = __fadd_rn(lo, b1s[2 * p]);
        z[2 * p + 1] = __fadd_rn(hi, b1s[2 * p + 1]);
    }
    float m = -3.0e38f;
#pragma unroll
    for (int j = 0; j < K_; j++) m = fmaxf(m, z[j]);
    float sum = 0.0f;
#pragma unroll
    for (int j = 0; j < K_; j++) {
        z[j] = __expf(__fadd_rn(z[j], -m));
        sum = __fadd_rn(sum, z[j]);
    }
    float inv = __fdiv_rn(1.0f, sum);

    int hw = t & (HW_ - 1);
    size_t out_base = ((size_t)((t >> 21) * K_ * R_ + r)) * HW_ + hw;

    float acc = 0.0f;
#pragma unroll
    for (int j = 0; j < K_; j++) {
        float cf = __fmul_rn(z[j], inv);
        acc = __fadd_rn(acc, __fmul_rn(rays[j], cf));
        __stcs(conf_out + out_base + (size_t)(j * R_) * HW_, cf);
    }
    __stcs(ray_out + t, fmaxf(acc, 0.0f));
}

extern "C" void kernel_launch(void* const* d_in, const int* in_sizes, int n_in,
                              void* d_out, int out_size)
{
    const float* sd       = (const float*)d_in[0];
    const float* features = (const float*)d_in[1];
    const float* w0       = (const float*)d_in[2];
    const float* w1       = (const float*)d_in[3];
    const float* b1       = (const float*)d_in[4];

    float* out      = (float*)d_out;
    float* ray_out  = out;
    float* conf_out = out + (size_t)B_ * R_ * HW_;

    const int SMEM_BYTES = SMEM_FLOATS * (int)sizeof(float);

    // One-time host-side objects (no device memory): second stream + events
    // for per-batch fork/join overlap of conf0(b+1) with refine(b).
    static cudaStream_t s2 = nullptr;
    static cudaEvent_t evA[B_];
    static cudaEvent_t evDone;
    if (!s2) {
        cudaStreamCreateWithFlags(&s2, cudaStreamNonBlocking);
        for (int i = 0; i < B_; i++)
            cudaEventCreateWithFlags(&evA[i], cudaEventDisableTiming);
        cudaEventCreateWithFlags(&evDone, cudaEventDisableTiming);
        cudaFuncSetAttribute(conf0_mma_kernel,
                             cudaFuncAttributeMaxDynamicSharedMemorySize, SMEM_BYTES);
    }

    for (int b = 0; b < B_; b++) {
        conf0_mma_kernel<<<HW_ / 512, 256, SMEM_BYTES>>>(features, w0, sd, b);
        cudaEventRecord(evA[b], 0);
        cudaStreamWaitEvent(s2, evA[b], 0);
        refine_kernel<<<(R_ * HW_) / 256, 256, 0, s2>>>(w1, b1, ray_out, conf_out, b);
    }
    cudaEventRecord(evDone, s2);
    cudaStreamWaitEvent(0, evDone, 0);
}

// round 16
// speedup vs baseline: 1.2848x; 1.2848x over previous
#include <cuda_runtime.h>

#define W_ 256
#define H_ 256
#define HW_ 65536
#define B_ 4
#define C_ 256
#define R_ 32
#define K_ 6

// 32 MB scratch for conf0 (B,R,H,W).
__device__ float g_conf0[B_ * R_ * HW_];
__device__ float g_sin[R_];
__device__ float g_cos[R_];

__constant__ float c_ef[5] = {0.2f, 0.4f, 0.6f, 0.8f, 1.0f};

__device__ __forceinline__ float tf32r(float x)
{
    unsigned u;
    asm("cvt.rna.tf32.f32 %0, %1;" : "=r"(u) : "f"(x));
    return __uint_as_float(u);
}

// ---- packed f32x2 helpers ----
__device__ __forceinline__ unsigned long long pack2(float lo, float hi)
{
    unsigned long long r;
    asm("mov.b64 %0, {%1, %2};" : "=l"(r) : "f"(lo), "f"(hi));
    return r;
}
__device__ __forceinline__ void unpack2(unsigned long long v, float& lo, float& hi)
{
    asm("mov.b64 {%0, %1}, %2;" : "=f"(lo), "=f"(hi) : "l"(v));
}
__device__ __forceinline__ unsigned long long mul2(unsigned long long a, unsigned long long b)
{
    unsigned long long d;
    asm("mul.rn.f32x2 %0, %1, %2;" : "=l"(d) : "l"(a), "l"(b));
    return d;
}
__device__ __forceinline__ unsigned long long add2(unsigned long long a, unsigned long long b)
{
    unsigned long long d;
    asm("add.rn.f32x2 %0, %1, %2;" : "=l"(d) : "l"(a), "l"(b));
    return d;
}
__device__ __forceinline__ void fma2(unsigned long long& d,
                                     unsigned long long a,
                                     unsigned long long b)
{
    asm("fma.rn.f32x2 %0, %1, %2, %0;" : "+l"(d) : "l"(a), "l"(b));
}

// ---- conf0: TF32 MMA, warp-private 3-stage cp.async pipeline (88 KB SMEM ->
// 2 CTAs/SM), SMEM-transpose epilogue -> coalesced STG.128 of conf0 only.
#define W0S_FLOATS (R_ * 257)
#define FS_ROW      72
#define FS_STAGE_W  (8 * FS_ROW)
#define FS_WSLICE   (3 * FS_STAGE_W)
#define FS_FLOATS   (8 * FS_WSLICE)
#define SMEM_FLOATS (W0S_FLOATS + FS_FLOATS)   // 88.2 KB
#define ES_ROW      68                         // 64 + 4 pad (16B-aligned rows)

__global__ __launch_bounds__(256) void conf0_mma_kernel(
    const float* __restrict__ features,
    const float* __restrict__ w0)
{
    extern __shared__ float smem[];
    float* w0s = smem;
    float* fs  = smem + W0S_FLOATS;

    if (blockIdx.x == 0 && threadIdx.x < R_) {
        int r = threadIdx.x;
        float ang = __fmul_rn(__fdiv_rn((float)r, 32.0f), 6.28318530717958647692f);
        g_sin[r] = sinf(ang);
        g_cos[r] = cosf(ang);
    }

    int tid  = threadIdx.x;
    int wi   = tid >> 5;
    int lane = tid & 31;
    int grp  = lane >> 2;
    int tg   = lane & 3;

    for (int i = tid; i < R_ * C_; i += 256)
        w0s[(i >> 8) * 257 + (i & 255)] = tf32r(w0[i]);
    __syncthreads();

    int gp   = blockIdx.x * 512;
    int b    = gp >> 16;
    int pix0 = (gp & (HW_ - 1)) + wi * 64;

    const float* fb = features + (size_t)b * C_ * HW_ + pix0;
    float* fwarp = fs + wi * FS_WSLICE;
    unsigned fsw = (unsigned)__cvta_generic_to_shared(fwarp);

    float c[2][8][4];
#pragma unroll
    for (int mt = 0; mt < 2; mt++)
#pragma unroll
        for (int nt = 0; nt < 8; nt++)
#pragma unroll
            for (int i = 0; i < 4; i++) c[mt][nt][i] = 0.0f;

#define LOAD_STAGE(st, ch0)                                                      \
    {                                                                            \
        _Pragma("unroll")                                                        \
        for (int i = 0; i < 4; i++) {                                            \
            int e   = lane + 32 * i;                                             \
            int row = e >> 4;                                                    \
            int f4  = e & 15;                                                    \
            const float* g = fb + (size_t)((ch0) + row) * HW_ + f4 * 4;          \
            unsigned s = fsw + (unsigned)(((st) * FS_STAGE_W + row * FS_ROW) * 4 + f4 * 16); \
            asm volatile("cp.async.cg.shared.global [%0], [%1], 16;"             \
                         :: "r"(s), "l"(g));                                     \
        }                                                                        \
    }

#pragma unroll
    for (int st = 0; st < 2; st++) {
        LOAD_STAGE(st, st * 8);
        asm volatile("cp.async.commit_group;");
    }

    int cur = 0;
#pragma unroll 4
    for (int k8 = 0; k8 < 32; k8++) {
        if (k8 + 2 < 32) {
            int stn = (k8 + 2) % 3;
            LOAD_STAGE(stn, (k8 + 2) * 8);
        }
        asm volatile("cp.async.commit_group;");
        asm volatile("cp.async.wait_group 2;");
        __syncwarp();

        const float* fcur = fwarp + cur * FS_STAGE_W;
        cur = (cur == 2) ? 0 : cur + 1;

        int ch = k8 * 8 + tg;
        unsigned a[2][4];
#pragma unroll
        for (int mt = 0; mt < 2; mt++) {
            int ray0 = mt * 16 + grp;
            a[mt][0] = __float_as_uint(w0s[ray0 * 257 + ch]);
            a[mt][1] = __float_as_uint(w0s[(ray0 + 8) * 257 + ch]);
            a[mt][2] = __float_as_uint(w0s[ray0 * 257 + ch + 4]);
            a[mt][3] = __float_as_uint(w0s[(ray0 + 8) * 257 + ch + 4]);
        }

#pragma unroll
        for (int nt = 0; nt < 8; nt++) {
            int col = nt * 8 + grp;
            unsigned b0 = __float_as_uint(tf32r(fcur[tg * FS_ROW + col]));
            unsigned b1 = __float_as_uint(tf32r(fcur[(tg + 4) * FS_ROW + col]));
#pragma unroll
            for (int mt = 0; mt < 2; mt++) {
                asm volatile(
                    "mma.sync.aligned.m16n8k8.row.col.f32.tf32.tf32.f32 "
                    "{%0,%1,%2,%3}, {%4,%5,%6,%7}, {%8,%9}, {%0,%1,%2,%3};"
                    : "+f"(c[mt][nt][0]), "+f"(c[mt][nt][1]),
                      "+f"(c[mt][nt][2]), "+f"(c[mt][nt][3])
                    : "r"(a[mt][0]), "r"(a[mt][1]), "r"(a[mt][2]), "r"(a[mt][3]),
                      "r"(b0), "r"(b1));
            }
        }
    }

    // SMEM-transpose epilogue: coalesced STG.128, 2 rays per pass per lane.
    float* obase = g_conf0 + (size_t)b * R_ * HW_ + pix0;
    float* es = fwarp;   // reuse stage buffer: 16*68 = 1088 <= 1728 floats

#pragma unroll
    for (int mt = 0; mt < 2; mt++) {
        __syncwarp();
#pragma unroll
        for (int nt = 0; nt < 8; nt++) {
            int col = nt * 8 + tg * 2;
            *(float2*)&es[grp * ES_ROW + col]       = make_float2(c[mt][nt][0], c[mt][nt][1]);
            *(float2*)&es[(grp + 8) * ES_ROW + col] = make_float2(c[mt][nt][2], c[mt][nt][3]);
        }
        __syncwarp();
#pragma unroll
        for (int rr = 0; rr < 16; rr += 2) {
            int lane16 = lane & 15;
            int half   = lane >> 4;         // 2 rays per pass: lanes 0-15 ray rr, 16-31 ray rr+1
            int ray = mt * 16 + rr + half;
            int px  = lane16 * 4;
            float4 cv = *(float4*)&es[(rr + half) * ES_ROW + px];
            *(float4*)(obase + (size_t)ray * HW_ + px) = cv;
        }
    }
}

// Kernel 2: fused refine — round 12 arithmetic (frozen) + __stcs streaming stores.
__global__ __launch_bounds__(256) void refine_kernel(
    const float* __restrict__ sd,
    const float* __restrict__ w1,
    const float* __restrict__ b1,
    float* __restrict__ ray_out,
    float* __restrict__ conf_out)
{
    __shared__ float2 w1p[K_ * 3];
    __shared__ float b1s[K_];
    if (threadIdx.x < K_ * 3) {
        int k = threadIdx.x / 3, p = threadIdx.x % 3;
        w1p[k * 3 + p] = make_float2(w1[(2 * p) * K_ + k], w1[(2 * p + 1) * K_ + k]);
    }
    if (threadIdx.x < K_) b1s[threadIdx.x] = b1[threadIdx.x];
    __syncthreads();

    int t = blockIdx.x * blockDim.x + threadIdx.x;
    int w = t & (W_ - 1);
    int h = (t >> 8) & (H_ - 1);
    int r = (t >> 16) & (R_ - 1);

    float s  = sd[t];
    float c0 = g_conf0[t];

    unsigned long long cssn = pack2(g_cos[r], g_sin[r]);
    unsigned long long wh   = pack2((float)w, (float)h);

    int plane = t & ~(HW_ - 1);
    const float* plane_s = sd + plane;
    const float* plane_c = g_conf0 + plane;

    float rays[K_], confs[K_];
    rays[0]  = s;
    confs[0] = c0;

    const float INV255 = 1.0f / 255.0f;
    const unsigned long long inv255_2 = pack2(INV255, INV255);
    const unsigned long long two2  = pack2(2.0f, 2.0f);
    const unsigned long long neg12 = pack2(-1.0f, -1.0f);
    const unsigned long long one2  = pack2(1.0f, 1.0f);
    const unsigned long long c2562 = pack2(256.0f, 256.0f);
    const unsigned long long half2 = pack2(0.5f, 0.5f);

#pragma unroll
    for (int e = 0; e < 5; e++) {
        float ef   = c_ef[e];
        float base = __fmul_rn(__fadd_rn(s, -1.0f), ef);
        unsigned long long base2 = pack2(base, base);
        unsigned long long g2 = add2(wh, mul2(cssn, base2));
        unsigned long long n2 = add2(mul2(mul2(g2, inv255_2), two2), neg12);
        unsigned long long i2 = mul2(add2(mul2(add2(n2, one2), c2562), neg12), half2);
        float ixf, iyf;
        unpack2(i2, ixf, iyf);
        int ix0 = __float2int_rn(ixf);
        int iy0 = __float2int_rn(iyf);
        bool valid = ((unsigned)ix0 < 256u) && ((unsigned)iy0 < 256u);
        int gi = valid ? (iy0 * W_ + ix0) : 0;
        float ss = plane_s[gi];
        float cc = plane_c[gi];
        ss = valid ? ss : 0.0f;
        cc = valid ? cc : 0.0f;
        rays[e + 1]  = __fadd_rn(ss, base);
        confs[e + 1] = cc;
    }

    unsigned long long zp[3];
    zp[0] = zp[1] = zp[2] = pack2(0.0f, 0.0f);
#pragma unroll
    for (int k = 0; k < K_; k++) {
        unsigned long long ck = pack2(confs[k], confs[k]);
#pragma unroll
        for (int p = 0; p < 3; p++) {
            float2 wv = w1p[k * 3 + p];
            fma2(zp[p], ck, pack2(wv.x, wv.y));
        }
    }
    float z[K_];
#pragma unroll
    for (int p = 0; p < 3; p++) {
        float lo, hi;
        unpack2(zp[p], lo, hi);
        z[2 * p]     = __fadd_rn(lo, b1s[2 * p]);
        z[2 * p + 1] = __fadd_rn(hi, b1s[2 * p + 1]);
    }
    float m = -3.0e38f;
#pragma unroll
    for (int j = 0; j < K_; j++) m = fmaxf(m, z[j]);
    float sum = 0.0f;
#pragma unroll
    for (int j = 0; j < K_; j++) {
        z[j] = __expf(__fadd_rn(z[j], -m));
        sum = __fadd_rn(sum, z[j]);
    }
    float inv = __fdiv_rn(1.0f, sum);

    int hw = t & (HW_ - 1);
    size_t out_base = ((size_t)((t >> 21) * K_ * R_ + r)) * HW_ + hw;

    float acc = 0.0f;
#pragma unroll
    for (int j = 0; j < K_; j++) {
        float cf = __fmul_rn(z[j], inv);
        acc = __fadd_rn(acc, __fmul_rn(rays[j], cf));
        __stcs(conf_out + out_base + (size_t)(j * R_) * HW_, cf);   // streaming
    }
    __stcs(ray_out + t, fmaxf(acc, 0.0f));
}

extern "C" void kernel_launch(void* const* d_in, const int* in_sizes, int n_in,
                              void* d_out, int out_size)
{
    const float* sd       = (const float*)d_in[0];
    const float* features = (const float*)d_in[1];
    const float* w0       = (const float*)d_in[2];
    const float* w1       = (const float*)d_in[3];
    const float* b1       = (const float*)d_in[4];

    float* out      = (float*)d_out;
    float* ray_out  = out;
    float* conf_out = out + (size_t)B_ * R_ * HW_;

    const int SMEM_BYTES = SMEM_FLOATS * (int)sizeof(float);   // 88.2 KB -> 2 CTAs/SM
    static int configured = 0;
    if (!configured) {
        cudaFuncSetAttribute(conf0_mma_kernel,
                             cudaFuncAttributeMaxDynamicSharedMemorySize, SMEM_BYTES);
        configured = 1;
    }

    conf0_mma_kernel<<<(B_ * HW_) / 512, 256, SMEM_BYTES>>>(features, w0);
    refine_kernel<<<(B_ * R_ * HW_) / 256, 256>>>(sd, w1, b1, ray_out, conf_out);
}